// round 13
// baseline (speedup 1.0000x reference)
#include <cuda_runtime.h>
#include <cstdint>

#define BQ 4096
#define HDIM 300
#define SEC 304          // per-section K (x-part or h-part)
#define KA 608           // total K
#define TT 64
#define NPAD 1216        // padded gate-cols (304 units x 4)
#define NCH 19           // K chunks of 32
#define STAGE 8192       // A1 2K | A2 2K | B1 2K | B2 2K (int8)
#define SMEMB (3 * STAGE)

// A digit planes: A = (a1*256+a2)*2^-14   (h quantized at 2^14)
__device__ __align__(128) int8_t g_Z1[(size_t)BQ * SEC];
__device__ __align__(128) int8_t g_Z2[(size_t)BQ * SEC];
__device__ __align__(128) int8_t g_H0a[2][(size_t)BQ * SEC];
__device__ __align__(128) int8_t g_H0b[2][(size_t)BQ * SEC];
__device__ __align__(128) int8_t g_H1a[2][(size_t)BQ * SEC];
__device__ __align__(128) int8_t g_H1b[2][(size_t)BQ * SEC];
// W digit planes: W = (b1*256+b2)*2^-17  (clamped to |W| <= 0.249)
__device__ __align__(128) int8_t g_B1[2][(size_t)NPAD * KA];
__device__ __align__(128) int8_t g_B2[2][(size_t)NPAD * KA];
__device__ __align__(128) float g_biasR[2][NPAD];
__device__ __align__(128) float g_c[2][(size_t)BQ * HDIM];

__device__ __forceinline__ uint32_t smem_u32(const void* p) {
    uint32_t a;
    asm("{ .reg .u64 t; cvta.to.shared.u64 t, %1; cvt.u32.u64 %0, t; }" : "=r"(a) : "l"(p));
    return a;
}
#define CP16(d, s) asm volatile("cp.async.cg.shared.global [%0], [%1], 16;" :: "r"((uint32_t)(d)), "l"(s) : "memory")
#define CP_COMMIT() asm volatile("cp.async.commit_group;" ::: "memory")
#define CP_WAIT(N) asm volatile("cp.async.wait_group " #N ";" ::: "memory")

// 32B-row staggered layout: off(row, half16) = row*32 + (half ^ ((row>>2)&1))*16.
__device__ __forceinline__ uint32_t qoff16(int row, int half) {
    return ((uint32_t)row << 5) + ((uint32_t)(half ^ ((row >> 2) & 1)) << 4);
}
__device__ __forceinline__ void ldsm4(uint32_t* r, uint32_t a) {
    asm volatile("ldmatrix.sync.aligned.m8n8.x4.shared.b16 {%0,%1,%2,%3}, [%4];"
                 : "=r"(r[0]), "=r"(r[1]), "=r"(r[2]), "=r"(r[3]) : "r"(a));
}
__device__ __forceinline__ void mma_s8(int32_t* d, const uint32_t* a, uint32_t b0, uint32_t b1) {
    asm volatile("mma.sync.aligned.m16n8k32.row.col.s32.s8.s8.s32 "
                 "{%0,%1,%2,%3}, {%4,%5,%6,%7}, {%8,%9}, {%0,%1,%2,%3};"
                 : "+r"(d[0]), "+r"(d[1]), "+r"(d[2]), "+r"(d[3])
                 : "r"(a[0]), "r"(a[1]), "r"(a[2]), "r"(a[3]), "r"(b0), "r"(b1));
}

// ---- FFMA-only transcendentals ----
__device__ __forceinline__ float exp_fast(float x) {
    x = fminf(fmaxf(x, -87.0f), 87.0f);
    float r = x * 1.4426950408889634f;
    float nf = r + 12582912.0f;
    int ni = __float_as_int(nf) - 0x4B400000;
    nf -= 12582912.0f;
    float f = fmaf(nf, -0.6931471824645996f, x);
    f = fmaf(nf, 1.9046542e-9f, f);
    float p = 1.9875691500e-4f;
    p = fmaf(p, f, 1.3981999507e-3f);
    p = fmaf(p, f, 8.3334519073e-3f);
    p = fmaf(p, f, 4.1665795894e-2f);
    p = fmaf(p, f, 1.6666665459e-1f);
    p = fmaf(p, f, 5.0000001201e-1f);
    p = fmaf(p, f, 1.0f);
    p = fmaf(p, f, 1.0f);
    return p * __int_as_float((ni + 127) << 23);
}
__device__ __forceinline__ float rcp_fast(float d) {
    float y = __int_as_float(0x7EF311C3 - __float_as_int(d));
    y = fmaf(fmaf(-d, y, 1.0f), y, y);
    y = fmaf(fmaf(-d, y, 1.0f), y, y);
    y = fmaf(fmaf(-d, y, 1.0f), y, y);
    return y;
}
__device__ __forceinline__ float sigmoid_fast(float x) { return rcp_fast(1.0f + exp_fast(-x)); }
__device__ __forceinline__ float tanh_fast(float x) {
    return fmaf(-2.0f, rcp_fast(exp_fast(2.0f * x) + 1.0f), 1.0f);
}

// ------- fused LSTM cell, int8 digit GEMM (4 products): CTA 64(M) x 64(N) -------
__global__ __launch_bounds__(256, 3)
void lstm_cell_i8(const int8_t* __restrict__ Ax1, const int8_t* __restrict__ Ax2,
                  const int8_t* __restrict__ Ah1, const int8_t* __restrict__ Ah2,
                  const int8_t* __restrict__ B1, const int8_t* __restrict__ B2,
                  const float* __restrict__ biasR, float* __restrict__ C,
                  int8_t* __restrict__ dst1, int8_t* __restrict__ dst2,
                  float* __restrict__ Y) {
    extern __shared__ __align__(1024) char smem[];
    const uint32_t sb = smem_u32(smem);
    const int tid = threadIdx.x, wid = tid >> 5, lane = tid & 31;
    const int mw = wid & 1;        // 2 M-warps x 32 rows
    const int nw = wid >> 1;       // 4 N-warps x 16 cols
    const int m0 = blockIdx.y * 64, nt = blockIdx.x;
    const int nbase = nt * 64;

    const int a_rin = lane & 15, a_half = lane >> 4;
    const int b_row = nw * 16 + (lane & 7) + ((lane >> 3) & 1) * 8;
    const int b_half = lane >> 4;
    const uint32_t b_off = 4096 + qoff16(b_row, b_half);

    int32_t acc1[2][2][4], acc2[2][2][4], acc3[2][2][4];
#pragma unroll
    for (int i = 0; i < 2; ++i)
#pragma unroll
        for (int j = 0; j < 2; ++j)
#pragma unroll
            for (int q = 0; q < 4; ++q) { acc1[i][j][q] = 0; acc2[i][j][q] = 0; acc3[i][j][q] = 0; }

    // stage loader: A1|A2|B1|B2 planes of 64 rows x 32B; 512 granules, 2/thread
    auto load_chunk = [&](int c, uint32_t bs) {
        const int k0 = c * 32;
#pragma unroll
        for (int j = 0; j < 2; ++j) {
            const int i = tid + j * 256;
            const int g = i & 127, row = g >> 1, hf = g & 1;
            const uint32_t dst = bs + (uint32_t)(i >> 7) * 2048 + qoff16(row, hf);
            if (i < 256) {
                const int k = k0 + hf * 16;
                const int sec = (k >= SEC);
                const int8_t* base = (i >> 7) ? (sec ? Ah2 : Ax2) : (sec ? Ah1 : Ax1);
                CP16(dst, base + (size_t)(m0 + row) * SEC + (k - (sec ? SEC : 0)));
            } else {
                const int8_t* base = ((i >> 7) & 1) ? B2 : B1;
                CP16(dst, base + (size_t)(nbase + row) * KA + k0 + hf * 16);
            }
        }
        CP_COMMIT();
    };

    load_chunk(0, sb);
    load_chunk(1, sb + STAGE);

#pragma unroll 1
    for (int c = 0; c < NCH; ++c) {
        if (c + 1 < NCH) { CP_WAIT(1); } else { CP_WAIT(0); }
        __syncthreads();

        const uint32_t bs = sb + (c % 3) * STAGE;
        uint32_t aoff[2];
#pragma unroll
        for (int mi = 0; mi < 2; ++mi)
            aoff[mi] = qoff16(mw * 32 + mi * 16 + a_rin, a_half);

        uint32_t A1f[2][4], B1f[4], B2f[4];
#pragma unroll
        for (int mi = 0; mi < 2; ++mi) ldsm4(A1f[mi], bs + aoff[mi]);
        ldsm4(B1f, bs + b_off);                    // B1 plane at +4096
        // P1: a1*b1 -> acc1
#pragma unroll
        for (int mi = 0; mi < 2; ++mi)
#pragma unroll
            for (int ni = 0; ni < 2; ++ni)
                mma_s8(acc1[mi][ni], A1f[mi], B1f[ni], B1f[ni + 2]);
        // P2: a1*b2 -> acc2
        ldsm4(B2f, bs + b_off + 2048);             // B2 plane at +6144
#pragma unroll
        for (int mi = 0; mi < 2; ++mi)
#pragma unroll
            for (int ni = 0; ni < 2; ++ni)
                mma_s8(acc2[mi][ni], A1f[mi], B2f[ni], B2f[ni + 2]);
        // P3: a2*b1 -> acc2 ; P4: a2*b2 -> acc3 (A2f reused, no extra ldsm)
        {
            uint32_t A2f[2][4];
#pragma unroll
            for (int mi = 0; mi < 2; ++mi) ldsm4(A2f[mi], bs + 2048 + aoff[mi]);
#pragma unroll
            for (int mi = 0; mi < 2; ++mi)
#pragma unroll
                for (int ni = 0; ni < 2; ++ni)
                    mma_s8(acc2[mi][ni], A2f[mi], B1f[ni], B1f[ni + 2]);
#pragma unroll
            for (int mi = 0; mi < 2; ++mi)
#pragma unroll
                for (int ni = 0; ni < 2; ++ni)
                    mma_s8(acc3[mi][ni], A2f[mi], B2f[ni], B2f[ni + 2]);
        }

        if (c + 2 < NCH) load_chunk(c + 2, sb + ((c + 2) % 3) * STAGE);
    }

    // ---- epilogue: combine digit accs, shfl gate-exchange, LSTM update ----
    const float C1 = 3.0517578125e-05f;        // 2^-15
    const float C2 = 1.1920928955078125e-07f;  // 2^-23
    const float C3 = 4.656612873077393e-10f;   // 2^-31
    const int odd = lane & 1;
#pragma unroll
    for (int mi = 0; mi < 2; ++mi) {
#pragma unroll
        for (int ni = 0; ni < 2; ++ni) {
            float v[4];
#pragma unroll
            for (int q = 0; q < 4; ++q)
                v[q] = fmaf((float)acc1[mi][ni][q], C1,
                            fmaf((float)acc2[mi][ni][q], C2, (float)acc3[mi][ni][q] * C3));
            const float e0 = __shfl_xor_sync(0xFFFFFFFFu, v[0], 1);
            const float e1 = __shfl_xor_sync(0xFFFFFFFFu, v[1], 1);
            const float e2 = __shfl_xor_sync(0xFFFFFFFFu, v[2], 1);
            const float e3 = __shfl_xor_sync(0xFFFFFFFFu, v[3], 1);
            float iv, fv, gv, ov;
            int rl;
            if (!odd) { iv = v[0]; fv = v[1]; gv = e0; ov = e1; rl = lane >> 2; }
            else      { iv = e2; fv = e3; gv = v[2]; ov = v[3]; rl = (lane >> 2) + 8; }
            const int u = nt * 16 + nw * 4 + ni * 2 + ((lane >> 1) & 1);
            if (u < HDIM) {
                const int m = m0 + mw * 32 + mi * 16 + rl;
                const float4 bb = *(const float4*)(biasR + 4 * u);
                iv += bb.x; fv += bb.y; gv += bb.z; ov += bb.w;
                const float ig = sigmoid_fast(iv);
                const float fg = sigmoid_fast(fv);
                const float gg = tanh_fast(gv);
                const float og = sigmoid_fast(ov);
                const size_t ci = (size_t)m * HDIM + u;
                const float cn = fmaf(fg, C[ci], ig * gg);
                C[ci] = cn;
                const float h = og * tanh_fast(cn);
                const int hv = __float2int_rn(h * 16384.0f);
                const int d1 = (hv + 128) >> 8;
                const int d2 = hv - (d1 << 8);
                const size_t ai = (size_t)m * SEC + u;
                dst1[ai] = (int8_t)d1;
                dst2[ai] = (int8_t)d2;
                if (Y) Y[(size_t)m * (TT * HDIM) + u] = h;
            }
        }
    }
}

// ---------------- prep kernels ----------------
__global__ void prep_weights(const float* __restrict__ Wih0, const float* __restrict__ Whh0,
                             const float* __restrict__ Wih1, const float* __restrict__ Whh1) {
    const int total = 2 * NPAD * KA;
    for (int idx = blockIdx.x * blockDim.x + threadIdx.x; idx < total; idx += gridDim.x * blockDim.x) {
        const int l = idx / (NPAD * KA), r2 = idx % (NPAD * KA);
        const int n = r2 / KA, k = r2 % KA;
        const int unit = n >> 2, gate = n & 3;
        const int kp = (k >= SEC), kk = k - (kp ? SEC : 0);
        float w = 0.f;
        if (unit < HDIM && kk < HDIM) {
            const float* W = l ? (kp ? Whh1 : Wih1) : (kp ? Whh0 : Wih0);
            w = W[(size_t)(gate * HDIM + unit) * HDIM + kk];
        }
        int v = __float2int_rn(w * 131072.0f);   // 2^17
        v = max(-32639, min(32639, v));
        const int b1 = (v + 128) >> 8;
        const int b2 = v - (b1 << 8);
        g_B1[l][(size_t)n * KA + k] = (int8_t)b1;
        g_B2[l][(size_t)n * KA + k] = (int8_t)b2;
    }
}

__global__ void prep_bias(const float* __restrict__ bih0, const float* __restrict__ bhh0,
                          const float* __restrict__ bih1, const float* __restrict__ bhh1) {
    for (int idx = blockIdx.x * blockDim.x + threadIdx.x; idx < 2 * NPAD; idx += gridDim.x * blockDim.x) {
        const int l = idx / NPAD, n = idx % NPAD;
        const int unit = n >> 2, gate = n & 3;
        float v = 0.f;
        if (unit < HDIM)
            v = l ? (bih1[gate * HDIM + unit] + bhh1[gate * HDIM + unit])
                  : (bih0[gate * HDIM + unit] + bhh0[gate * HDIM + unit]);
        g_biasR[l][n] = v;
    }
}

__global__ void init_state(const float* __restrict__ z) {
    const size_t total = (size_t)BQ * SEC;
    for (size_t idx = blockIdx.x * (size_t)blockDim.x + threadIdx.x; idx < total;
         idx += gridDim.x * (size_t)blockDim.x) {
        const int row = (int)(idx / SEC), col = (int)(idx % SEC);
        float v = (col < HDIM) ? z[(size_t)row * HDIM + col] : 0.f;
        const int q = __float2int_rn(v * 16384.0f);   // z in [0,1] -> fits (16384 = 64*256)
        const int d1 = (q + 128) >> 8;
        const int d2 = q - (d1 << 8);
        g_Z1[idx] = (int8_t)d1;
        g_Z2[idx] = (int8_t)d2;
        g_H0a[0][idx] = 0; g_H0b[0][idx] = 0;
        g_H0a[1][idx] = 0; g_H0b[1][idx] = 0;
        g_H1a[0][idx] = 0; g_H1b[0][idx] = 0;
        g_H1a[1][idx] = 0; g_H1b[1][idx] = 0;
        if (col < HDIM) {
            g_c[0][(size_t)row * HDIM + col] = 0.f;
            g_c[1][(size_t)row * HDIM + col] = 0.f;
        }
    }
}

// ---------------- host ----------------
extern "C" void kernel_launch(void* const* d_in, const int* in_sizes, int n_in,
                              void* d_out, int out_size) {
    const float* z    = (const float*)d_in[0];
    const float* Wih0 = (const float*)d_in[1];
    const float* Whh0 = (const float*)d_in[2];
    const float* bih0 = (const float*)d_in[3];
    const float* bhh0 = (const float*)d_in[4];
    const float* Wih1 = (const float*)d_in[5];
    const float* Whh1 = (const float*)d_in[6];
    const float* bih1 = (const float*)d_in[7];
    const float* bhh1 = (const float*)d_in[8];
    float* out = (float*)d_out;

    int8_t *Z1, *Z2, *H0a, *H0b, *H1a, *H1b, *B1, *B2;
    float *biasR, *cst;
    cudaGetSymbolAddress((void**)&Z1, g_Z1);
    cudaGetSymbolAddress((void**)&Z2, g_Z2);
    cudaGetSymbolAddress((void**)&H0a, g_H0a);
    cudaGetSymbolAddress((void**)&H0b, g_H0b);
    cudaGetSymbolAddress((void**)&H1a, g_H1a);
    cudaGetSymbolAddress((void**)&H1b, g_H1b);
    cudaGetSymbolAddress((void**)&B1, g_B1);
    cudaGetSymbolAddress((void**)&B2, g_B2);
    cudaGetSymbolAddress((void**)&biasR, g_biasR);
    cudaGetSymbolAddress((void**)&cst, g_c);

    cudaFuncSetAttribute(lstm_cell_i8, cudaFuncAttributeMaxDynamicSharedMemorySize, SMEMB);

    prep_weights<<<2048, 256>>>(Wih0, Whh0, Wih1, Whh1);
    prep_bias<<<10, 256>>>(bih0, bhh0, bih1, bhh1);
    init_state<<<2048, 256>>>(z);

    const size_t SN = (size_t)BQ * SEC;
    const size_t BN = (size_t)NPAD * KA;
    const size_t CN = (size_t)BQ * HDIM;
    dim3 grid(19, 64);   // 19 N-tiles(64 gate-cols) x 64 M-tiles(64 rows) = 1216 CTAs
    for (int t = 0; t < TT; ++t) {
        const int p = t & 1, q = p ^ 1;
        // layer 0: x-sec = (t? h1[p] : z), h-sec = h0[p]; writes h0 -> H0[q]
        lstm_cell_i8<<<grid, 256, SMEMB>>>(
            t ? (H1a + p * SN) : Z1, t ? (H1b + p * SN) : Z2,
            H0a + p * SN, H0b + p * SN,
            B1, B2, biasR, cst,
            H0a + q * SN, H0b + q * SN, nullptr);
        // layer 1: x-sec = fresh h0 = H0[q], h-sec = h1[p]; writes h1 -> H1[q]; emits Y
        lstm_cell_i8<<<grid, 256, SMEMB>>>(
            H0a + q * SN, H0b + q * SN,
            H1a + p * SN, H1b + p * SN,
            B1 + BN, B2 + BN, biasR + NPAD, cst + CN,
            H1a + q * SN, H1b + q * SN, out + (size_t)t * HDIM);
    }
}

// round 14
// speedup vs baseline: 2.4402x; 2.4402x over previous
#include <cuda_runtime.h>
#include <cuda_fp16.h>
#include <cstdint>

#define BQ 4096
#define HDIM 300
#define SEC 304          // per-section K (x-part or h-part)
#define KA 608           // total K
#define TT 64
#define NPAD 1216        // padded gate-cols (304 units x 4)
#define NCH 19           // K chunks of 32
#define STAGE 16384      // Ahi 4K | Alo 4K | Bhi 4K | Blo 4K
#define SMEMB (3 * STAGE)

__device__ __align__(128) __half g_Zhi[(size_t)BQ * SEC];
__device__ __align__(128) __half g_Zlo[(size_t)BQ * SEC];
__device__ __align__(128) __half g_H0hi[2][(size_t)BQ * SEC];
__device__ __align__(128) __half g_H0lo[2][(size_t)BQ * SEC];
__device__ __align__(128) __half g_H1hi[2][(size_t)BQ * SEC];
__device__ __align__(128) __half g_H1lo[2][(size_t)BQ * SEC];
__device__ __align__(128) __half g_Bhi[2][(size_t)NPAD * KA];
__device__ __align__(128) __half g_Blo[2][(size_t)NPAD * KA];
__device__ __align__(128) float g_biasR[2][NPAD];
__device__ __align__(128) float g_c[2][(size_t)BQ * HDIM];

__device__ __forceinline__ uint32_t smem_u32(const void* p) {
    uint32_t a;
    asm("{ .reg .u64 t; cvta.to.shared.u64 t, %1; cvt.u32.u64 %0, t; }" : "=r"(a) : "l"(p));
    return a;
}
#define CP16(d, s) asm volatile("cp.async.cg.shared.global [%0], [%1], 16;" :: "r"((uint32_t)(d)), "l"(s) : "memory")
#define CP_COMMIT() asm volatile("cp.async.commit_group;" ::: "memory")
#define CP_WAIT(N) asm volatile("cp.async.wait_group " #N ";" ::: "memory")

// paired-row swizzle: rows are 32 halves (64B); two rows share a 128B atom row
__device__ __forceinline__ uint32_t swzoff(int row, int colh) {
    uint32_t o = ((uint32_t)(row >> 1) << 7) + ((uint32_t)(row & 1) << 6) + ((uint32_t)colh << 1);
    return o ^ ((o >> 3) & 0x70);
}
__device__ __forceinline__ void ldsm4(uint32_t* r, uint32_t a) {
    asm volatile("ldmatrix.sync.aligned.m8n8.x4.shared.b16 {%0,%1,%2,%3}, [%4];"
                 : "=r"(r[0]), "=r"(r[1]), "=r"(r[2]), "=r"(r[3]) : "r"(a));
}
// f32-accumulator HMMA (hi product)
__device__ __forceinline__ void mma16816(float* d, const uint32_t* a, const uint32_t* b) {
    asm volatile("mma.sync.aligned.m16n8k16.row.col.f32.f16.f16.f32 "
                 "{%0,%1,%2,%3}, {%4,%5,%6,%7}, {%8,%9}, {%0,%1,%2,%3};"
                 : "+f"(d[0]), "+f"(d[1]), "+f"(d[2]), "+f"(d[3])
                 : "r"(a[0]), "r"(a[1]), "r"(a[2]), "r"(a[3]), "r"(b[0]), "r"(b[1]));
}
// f16-accumulator HMMA (lo products; D=C packed f16x2 pairs)
__device__ __forceinline__ void mma16816h(uint32_t* d, const uint32_t* a, const uint32_t* b) {
    asm volatile("mma.sync.aligned.m16n8k16.row.col.f16.f16.f16.f16 "
                 "{%0,%1}, {%2,%3,%4,%5}, {%6,%7}, {%0,%1};"
                 : "+r"(d[0]), "+r"(d[1])
                 : "r"(a[0]), "r"(a[1]), "r"(a[2]), "r"(a[3]), "r"(b[0]), "r"(b[1]));
}

// ---- FFMA-only transcendentals ----
__device__ __forceinline__ float exp_fast(float x) {
    x = fminf(fmaxf(x, -87.0f), 87.0f);
    float r = x * 1.4426950408889634f;
    float nf = r + 12582912.0f;
    int ni = __float_as_int(nf) - 0x4B400000;
    nf -= 12582912.0f;
    float f = fmaf(nf, -0.6931471824645996f, x);
    f = fmaf(nf, 1.9046542e-9f, f);
    float p = 1.9875691500e-4f;
    p = fmaf(p, f, 1.3981999507e-3f);
    p = fmaf(p, f, 8.3334519073e-3f);
    p = fmaf(p, f, 4.1665795894e-2f);
    p = fmaf(p, f, 1.6666665459e-1f);
    p = fmaf(p, f, 5.0000001201e-1f);
    p = fmaf(p, f, 1.0f);
    p = fmaf(p, f, 1.0f);
    return p * __int_as_float((ni + 127) << 23);
}
__device__ __forceinline__ float rcp_fast(float d) {
    float y = __int_as_float(0x7EF311C3 - __float_as_int(d));
    y = fmaf(fmaf(-d, y, 1.0f), y, y);
    y = fmaf(fmaf(-d, y, 1.0f), y, y);
    y = fmaf(fmaf(-d, y, 1.0f), y, y);
    return y;
}
__device__ __forceinline__ float sigmoid_fast(float x) { return rcp_fast(1.0f + exp_fast(-x)); }
__device__ __forceinline__ float tanh_fast(float x) {
    return fmaf(-2.0f, rcp_fast(exp_fast(2.0f * x) + 1.0f), 1.0f);
}

// ------- fused LSTM cell: CTA 64(M) x 64(N gate-cols), 8 warps of 32x16 -------
__global__ __launch_bounds__(256, 4)
void lstm_cell_mma(const __half* __restrict__ Axhi, const __half* __restrict__ Axlo,
                   const __half* __restrict__ Ahhi, const __half* __restrict__ Ahlo,
                   const __half* __restrict__ Bhi, const __half* __restrict__ Blo,
                   const float* __restrict__ biasR, float* __restrict__ C,
                   __half* __restrict__ dsthi, __half* __restrict__ dstlo,
                   float* __restrict__ Y) {
    extern __shared__ __align__(1024) char smem[];
    const uint32_t sb = smem_u32(smem);
    const int tid = threadIdx.x, wid = tid >> 5, lane = tid & 31;
    const int mw = wid & 1;        // 2 M-warps x 32 rows
    const int nw = wid >> 1;       // 4 N-warps x 16 cols
    const int m0 = blockIdx.y * 64, nt = blockIdx.x;
    const int nbase = nt * 64;

    const int a_r = mw * 32 + (lane & 7) + ((lane >> 3) & 1) * 8;
    const int a_c = ((lane >> 4) & 1) * 8;
    const int b_r = nw * 16 + (lane & 7) + ((lane >> 4) & 1) * 8;
    const int b_c = ((lane >> 3) & 1) * 8;

    float accH[2][2][4];           // hi product, f32 acc
    uint32_t accL[2][2][2];        // lo products, f16 acc (packed f16x2 pairs)
#pragma unroll
    for (int i = 0; i < 2; ++i)
#pragma unroll
        for (int j = 0; j < 2; ++j) {
#pragma unroll
            for (int q = 0; q < 4; ++q) accH[i][j][q] = 0.0f;
            accL[i][j][0] = 0u; accL[i][j][1] = 0u;
        }

    // stage loader: Ahi(64x32)|Alo|Bhi(64x32)|Blo, 1024 granules, 4/thread
    auto load_chunk = [&](int c, uint32_t bs) {
        const int k0 = c * 32;
#pragma unroll
        for (int j = 0; j < 4; ++j) {
            const int i = tid + j * 256;
            const int g = i & 255, row = g >> 2, cb = g & 3;
            if (i < 512) {
                const int part = i >> 8;               // 0=hi 1=lo
                const int k = k0 + cb * 8;
                const int sec = (k >= SEC);
                const __half* base = part ? (sec ? Ahlo : Axlo) : (sec ? Ahhi : Axhi);
                CP16(bs + part * 4096 + swzoff(row, cb * 8),
                     base + (size_t)(m0 + row) * SEC + (k - (sec ? SEC : 0)));
            } else {
                const int part = (i >> 8) & 1;         // 0=hi 1=lo
                const __half* base = part ? Blo : Bhi;
                CP16(bs + 8192 + part * 4096 + swzoff(row, cb * 8),
                     base + (size_t)(nbase + row) * KA + k0 + cb * 8);
            }
        }
        CP_COMMIT();
    };

    load_chunk(0, sb);
    load_chunk(1, sb + STAGE);

#pragma unroll 1
    for (int c = 0; c < NCH; ++c) {
        if (c + 1 < NCH) { CP_WAIT(1); } else { CP_WAIT(0); }
        __syncthreads();

        const uint32_t bs = sb + (c % 3) * STAGE;
        const uint32_t tAhi = bs, tAlo = bs + 4096, tBhi = bs + 8192, tBlo = bs + 12288;
#pragma unroll
        for (int ks = 0; ks < 2; ++ks) {
            uint32_t Ah[2][4], Bh[4];
#pragma unroll
            for (int mi = 0; mi < 2; ++mi) ldsm4(Ah[mi], tAhi + swzoff(a_r + mi * 16, a_c + ks * 16));
            ldsm4(Bh, tBhi + swzoff(b_r, b_c + ks * 16));
            // P1 (hi): Ah*Bh -> f32 acc
#pragma unroll
            for (int mi = 0; mi < 2; ++mi)
#pragma unroll
                for (int ni = 0; ni < 2; ++ni)
                    mma16816(accH[mi][ni], Ah[mi], &Bh[ni * 2]);
            {   // P2 (lo): Al*Bh -> f16 acc
                uint32_t Al[2][4];
#pragma unroll
                for (int mi = 0; mi < 2; ++mi) ldsm4(Al[mi], tAlo + swzoff(a_r + mi * 16, a_c + ks * 16));
#pragma unroll
                for (int mi = 0; mi < 2; ++mi)
#pragma unroll
                    for (int ni = 0; ni < 2; ++ni)
                        mma16816h(accL[mi][ni], Al[mi], &Bh[ni * 2]);
            }
            {   // P3 (lo): Ah*Bl -> f16 acc
                uint32_t Bl[4];
                ldsm4(Bl, tBlo + swzoff(b_r, b_c + ks * 16));
#pragma unroll
                for (int mi = 0; mi < 2; ++mi)
#pragma unroll
                    for (int ni = 0; ni < 2; ++ni)
                        mma16816h(accL[mi][ni], Ah[mi], &Bl[ni * 2]);
            }
        }
        if (c + 2 < NCH) load_chunk(c + 2, sb + ((c + 2) % 3) * STAGE);
    }

    // ---- epilogue: combine hi(f32)+lo(f16) accs, shfl gate-exchange, LSTM update ----
    const int odd = lane & 1;
#pragma unroll
    for (int mi = 0; mi < 2; ++mi) {
#pragma unroll
        for (int ni = 0; ni < 2; ++ni) {
            const float2 l01 = __half22float2(*reinterpret_cast<__half2*>(&accL[mi][ni][0]));
            const float2 l23 = __half22float2(*reinterpret_cast<__half2*>(&accL[mi][ni][1]));
            float v[4];
            v[0] = accH[mi][ni][0] + l01.x;
            v[1] = accH[mi][ni][1] + l01.y;
            v[2] = accH[mi][ni][2] + l23.x;
            v[3] = accH[mi][ni][3] + l23.y;
            const float e0 = __shfl_xor_sync(0xFFFFFFFFu, v[0], 1);
            const float e1 = __shfl_xor_sync(0xFFFFFFFFu, v[1], 1);
            const float e2 = __shfl_xor_sync(0xFFFFFFFFu, v[2], 1);
            const float e3 = __shfl_xor_sync(0xFFFFFFFFu, v[3], 1);
            float iv, fv, gv, ov;
            int rl;
            if (!odd) { iv = v[0]; fv = v[1]; gv = e0; ov = e1; rl = lane >> 2; }
            else      { iv = e2; fv = e3; gv = v[2]; ov = v[3]; rl = (lane >> 2) + 8; }
            const int u = nt * 16 + nw * 4 + ni * 2 + ((lane >> 1) & 1);
            if (u < HDIM) {
                const int m = m0 + mw * 32 + mi * 16 + rl;
                const float4 bb = *(const float4*)(biasR + 4 * u);
                iv += bb.x; fv += bb.y; gv += bb.z; ov += bb.w;
                const float ig = sigmoid_fast(iv);
                const float fg = sigmoid_fast(fv);
                const float gg = tanh_fast(gv);
                const float og = sigmoid_fast(ov);
                const size_t ci = (size_t)m * HDIM + u;
                const float cn = fmaf(fg, C[ci], ig * gg);
                C[ci] = cn;
                const float h = og * tanh_fast(cn);
                const __half hh = __float2half_rn(h);
                const __half hl = __float2half_rn(h - __half2float(hh));
                const size_t ai = (size_t)m * SEC + u;
                dsthi[ai] = hh; dstlo[ai] = hl;
                if (Y) Y[(size_t)m * (TT * HDIM) + u] = h;
            }
        }
    }
}

// ---------------- prep kernels ----------------
__global__ void prep_weights(const float* __restrict__ Wih0, const float* __restrict__ Whh0,
                             const float* __restrict__ Wih1, const float* __restrict__ Whh1) {
    const int total = 2 * NPAD * KA;
    for (int idx = blockIdx.x * blockDim.x + threadIdx.x; idx < total; idx += gridDim.x * blockDim.x) {
        const int l = idx / (NPAD * KA), r2 = idx % (NPAD * KA);
        const int n = r2 / KA, k = r2 % KA;
        const int unit = n >> 2, gate = n & 3;
        const int kp = (k >= SEC), kk = k - (kp ? SEC : 0);
        float w = 0.f;
        if (unit < HDIM && kk < HDIM) {
            const float* W = l ? (kp ? Whh1 : Wih1) : (kp ? Whh0 : Wih0);
            w = W[(size_t)(gate * HDIM + unit) * HDIM + kk];
        }
        const __half hi = __float2half_rn(w);
        g_Bhi[l][(size_t)n * KA + k] = hi;
        g_Blo[l][(size_t)n * KA + k] = __float2half_rn(w - __half2float(hi));
    }
}

__global__ void prep_bias(const float* __restrict__ bih0, const float* __restrict__ bhh0,
                          const float* __restrict__ bih1, const float* __restrict__ bhh1) {
    for (int idx = blockIdx.x * blockDim.x + threadIdx.x; idx < 2 * NPAD; idx += gridDim.x * blockDim.x) {
        const int l = idx / NPAD, n = idx % NPAD;
        const int unit = n >> 2, gate = n & 3;
        float v = 0.f;
        if (unit < HDIM)
            v = l ? (bih1[gate * HDIM + unit] + bhh1[gate * HDIM + unit])
                  : (bih0[gate * HDIM + unit] + bhh0[gate * HDIM + unit]);
        g_biasR[l][n] = v;
    }
}

__global__ void init_state(const float* __restrict__ z) {
    const __half zh = __float2half_rn(0.f);
    const size_t total = (size_t)BQ * SEC;
    for (size_t idx = blockIdx.x * (size_t)blockDim.x + threadIdx.x; idx < total;
         idx += gridDim.x * (size_t)blockDim.x) {
        const int row = (int)(idx / SEC), col = (int)(idx % SEC);
        float v = (col < HDIM) ? z[(size_t)row * HDIM + col] : 0.f;
        const __half hi = __float2half_rn(v);
        g_Zhi[idx] = hi;
        g_Zlo[idx] = __float2half_rn(v - __half2float(hi));
        g_H0hi[0][idx] = zh; g_H0lo[0][idx] = zh;
        g_H0hi[1][idx] = zh; g_H0lo[1][idx] = zh;
        g_H1hi[0][idx] = zh; g_H1lo[0][idx] = zh;
        g_H1hi[1][idx] = zh; g_H1lo[1][idx] = zh;
        if (col < HDIM) {
            g_c[0][(size_t)row * HDIM + col] = 0.f;
            g_c[1][(size_t)row * HDIM + col] = 0.f;
        }
    }
}

// ---------------- host ----------------
extern "C" void kernel_launch(void* const* d_in, const int* in_sizes, int n_in,
                              void* d_out, int out_size) {
    const float* z    = (const float*)d_in[0];
    const float* Wih0 = (const float*)d_in[1];
    const float* Whh0 = (const float*)d_in[2];
    const float* bih0 = (const float*)d_in[3];
    const float* bhh0 = (const float*)d_in[4];
    const float* Wih1 = (const float*)d_in[5];
    const float* Whh1 = (const float*)d_in[6];
    const float* bih1 = (const float*)d_in[7];
    const float* bhh1 = (const float*)d_in[8];
    float* out = (float*)d_out;

    __half *Zhi, *Zlo, *H0hi, *H0lo, *H1hi, *H1lo, *Bhi, *Blo;
    float *biasR, *cst;
    cudaGetSymbolAddress((void**)&Zhi, g_Zhi);
    cudaGetSymbolAddress((void**)&Zlo, g_Zlo);
    cudaGetSymbolAddress((void**)&H0hi, g_H0hi);
    cudaGetSymbolAddress((void**)&H0lo, g_H0lo);
    cudaGetSymbolAddress((void**)&H1hi, g_H1hi);
    cudaGetSymbolAddress((void**)&H1lo, g_H1lo);
    cudaGetSymbolAddress((void**)&Bhi, g_Bhi);
    cudaGetSymbolAddress((void**)&Blo, g_Blo);
    cudaGetSymbolAddress((void**)&biasR, g_biasR);
    cudaGetSymbolAddress((void**)&cst, g_c);

    cudaFuncSetAttribute(lstm_cell_mma, cudaFuncAttributeMaxDynamicSharedMemorySize, SMEMB);

    prep_weights<<<2048, 256>>>(Wih0, Whh0, Wih1, Whh1);
    prep_bias<<<10, 256>>>(bih0, bhh0, bih1, bhh1);
    init_state<<<2048, 256>>>(z);

    const size_t SN = (size_t)BQ * SEC;
    const size_t BN = (size_t)NPAD * KA;
    const size_t CN = (size_t)BQ * HDIM;
    dim3 grid(19, 64);   // 19 N-tiles(64 gate-cols) x 64 M-tiles(64 rows) = 1216 CTAs
    for (int t = 0; t < TT; ++t) {
        const int p = t & 1, q = p ^ 1;
        // layer 0: x-sec = (t? h1[p] : z), h-sec = h0[p]; writes h0 -> H0[q]
        lstm_cell_mma<<<grid, 256, SMEMB>>>(
            t ? (H1hi + p * SN) : Zhi, t ? (H1lo + p * SN) : Zlo,
            H0hi + p * SN, H0lo + p * SN,
            Bhi, Blo, biasR, cst,
            H0hi + q * SN, H0lo + q * SN, nullptr);
        // layer 1: x-sec = fresh h0 = H0[q], h-sec = h1[p]; writes h1 -> H1[q]; emits Y
        lstm_cell_mma<<<grid, 256, SMEMB>>>(
            H0hi + q * SN, H0lo + q * SN,
            H1hi + p * SN, H1lo + p * SN,
            Bhi + BN, Blo + BN, biasR + NPAD, cst + CN,
            H1hi + q * SN, H1lo + q * SN, out + (size_t)t * HDIM);
    }
}